// round 6
// baseline (speedup 1.0000x reference)
#include <cuda_runtime.h>
#include <cfloat>

// xp: (32, 64, 64, 512) fp32, m innermost. out: (32, 48*512), bin = iw*6+ih.
// Resize is identity. Row bins: 8 rows each. Col edges: {0,11,21,32,43,53,64}.
//
// R6: R3 (the 42.6us / 78.2% DRAM operating point) with block granularity
// halved for tail smoothing: each block = one (b, bin, row-half) of 4 rows,
// grid 96x32 = 3072 blocks (~12us lifetime each). During the end-of-kernel
// drain, finer quanta keep enough loads in flight to hold DRAM saturation.
// Inner loop identical to R3: 2-row interleave x fully-unrolled columns
// (MLP ~20 per thread), which measured best across R1-R5.

#define B_DIM 32
#define W_DIM 64
#define H_DIM 64
#define M_DIM 512
#define W_BINS 8
#define H_BINS 6
#define M4 (M_DIM / 4)            // 128 float4 lanes per (b,r,c)
#define ROW_STRIDE (H_DIM * M4)   // float4 elems per image row

__constant__ int C_EDGE[H_BINS + 1] = {0, 11, 21, 32, 43, 53, 64};

static __device__ __forceinline__ float4 fmax4(float4 a, float4 b) {
    a.x = fmaxf(a.x, b.x);
    a.y = fmaxf(a.y, b.y);
    a.z = fmaxf(a.z, b.z);
    a.w = fmaxf(a.w, b.w);
    return a;
}

// Block = (bin, b, half). 128 threads; thread t owns channels [4t, 4t+4).
// Half h covers rows [iw*8 + 4h, iw*8 + 4h + 4). The two halves of a bin
// combine via one fp32 max merge into the same output slot -- done without
// atomics by having half 0 write first? No: halves run concurrently, so each
// half reduces 4 rows and we merge through gmem with a deterministic
// two-kernel-free scheme: half 0 and half 1 write to distinct scratch-free
// locations is impossible -- instead we keep it simple: grid.z selects the
// half and we do an atomicMax-free merge by having each (b,bin) OWN one
// output slot per half in a __device__ scratch, then a tiny combine kernel.
// Simpler and cheaper: skip scratch -- each block reduces 4 rows and merges
// into d_out with 32-bit atomicMax on the float bit-pattern. All inputs are
// finite normals from randn; for floats >=0 bit-pattern order matches float
// order, for negatives it inverts -- NOT safe. So: scratch + combine kernel.

__device__ float4 g_scratch[2][B_DIM * W_BINS * H_BINS * M4];

__global__ __launch_bounds__(M4, 8)
void adaptive_maxpool_half_kernel(const float4* __restrict__ x4) {
    const int bin  = blockIdx.x;      // 0..47  (iw*6 + ih)
    const int b    = blockIdx.y;      // 0..31
    const int half = blockIdx.z;      // 0..1
    const int iw   = bin / H_BINS;
    const int ih   = bin - iw * H_BINS;

    const int r1 = iw * (W_DIM / W_BINS) + half * 4;  // 4 rows per block
    const int c1 = C_EDGE[ih];
    const bool has11 = (C_EDGE[ih + 1] - c1) == 11;   // widths are 10 or 11

    const int t = threadIdx.x;                        // 0..127
    const float4* base =
        x4 + ((size_t)(b * W_DIM + r1) * H_DIM + c1) * M4 + t;

    float4 acc = make_float4(-FLT_MAX, -FLT_MAX, -FLT_MAX, -FLT_MAX);

    // 4 rows as 2 row-pairs; per pair 2x10 (+2) independent loads in flight.
    #pragma unroll 1
    for (int rp = 0; rp < 2; ++rp) {
        const float4* r0 = base + (size_t)(2 * rp) * ROW_STRIDE;
        const float4* r1p = r0 + ROW_STRIDE;

        #pragma unroll
        for (int c = 0; c < 10; ++c) {
            float4 va = __ldcs(r0  + (size_t)c * M4);
            float4 vb = __ldcs(r1p + (size_t)c * M4);
            acc = fmax4(acc, fmax4(va, vb));
        }
        if (has11) {
            float4 va = __ldcs(r0  + (size_t)10 * M4);
            float4 vb = __ldcs(r1p + (size_t)10 * M4);
            acc = fmax4(acc, fmax4(va, vb));
        }
    }

    g_scratch[half][((size_t)b * (W_BINS * H_BINS) + bin) * M4 + t] = acc;
}

// Tiny combine: 1.5M floats read from scratch (L2-resident), 0.75M written.
__global__ __launch_bounds__(256)
void combine_halves_kernel(float4* __restrict__ out4) {
    const size_t i = (size_t)blockIdx.x * blockDim.x + threadIdx.x;
    const size_t n = (size_t)B_DIM * W_BINS * H_BINS * M4;
    if (i < n) {
        out4[i] = fmax4(g_scratch[0][i], g_scratch[1][i]);
    }
}

extern "C" void kernel_launch(void* const* d_in, const int* in_sizes, int n_in,
                              void* d_out, int out_size) {
    (void)in_sizes; (void)n_in; (void)out_size;
    const float4* x4 = (const float4*)d_in[0];
    float4* o4 = (float4*)d_out;

    dim3 grid(W_BINS * H_BINS, B_DIM, 2);   // (48, 32, 2) = 3072 blocks
    adaptive_maxpool_half_kernel<<<grid, M4>>>(x4);

    const int n = B_DIM * W_BINS * H_BINS * M4;   // 196608 float4
    combine_halves_kernel<<<(n + 255) / 256, 256>>>(o4);
}

// round 7
// speedup vs baseline: 1.0871x; 1.0871x over previous
#include <cuda_runtime.h>
#include <cfloat>

// xp: (32, 64, 64, 512) fp32, m innermost. out: (32, 48*512), bin = iw*6+ih.
// Resize is identity. Row bins: 8 rows each. Col edges: {0,11,21,32,43,53,64}.
//
// R7: R3's proven streaming loop (78.2% DRAM, best so far) with R6's finer
// work granularity folded INTO one block: 256 threads = 2 row-halves x 128
// channel lanes. Each half reduces 4 rows (2 row-pairs, unrolled 10/11 cols,
// MLP ~20); halves merge via 2KB smem. Thread lifetime halves vs R3 ->
// shorter end-of-kernel drain, with no extra kernel and no extra traffic
// (R6 showed the drain gain is ~0.8us but its serial combine cost 5.3us).

#define B_DIM 32
#define W_DIM 64
#define H_DIM 64
#define M_DIM 512
#define W_BINS 8
#define H_BINS 6
#define M4 (M_DIM / 4)            // 128 float4 lanes per (b,r,c)
#define ROW_STRIDE (H_DIM * M4)   // float4 elems per image row

__constant__ int C_EDGE[H_BINS + 1] = {0, 11, 21, 32, 43, 53, 64};

static __device__ __forceinline__ float4 fmax4(float4 a, float4 b) {
    a.x = fmaxf(a.x, b.x);
    a.y = fmaxf(a.y, b.y);
    a.z = fmaxf(a.z, b.z);
    a.w = fmaxf(a.w, b.w);
    return a;
}

// Block = (bin, b). 256 threads: half = t>>7 covers rows [r1+4*half, +4),
// lane = t&127 owns channels [4*lane, 4*lane+4).
__global__ __launch_bounds__(2 * M4)
void adaptive_maxpool_kernel(const float4* __restrict__ x4,
                             float4* __restrict__ out4) {
    const int bin = blockIdx.x;       // 0..47  (iw*6 + ih)
    const int b   = blockIdx.y;       // 0..31
    const int iw  = bin / H_BINS;
    const int ih  = bin - iw * H_BINS;

    const int t    = threadIdx.x;     // 0..255
    const int lane = t & (M4 - 1);    // 0..127
    const int half = t >> 7;          // 0..1

    const int r1 = iw * (W_DIM / W_BINS) + half * 4;  // this half's 4 rows
    const int c1 = C_EDGE[ih];
    const bool has11 = (C_EDGE[ih + 1] - c1) == 11;   // widths are 10 or 11

    const float4* base =
        x4 + ((size_t)(b * W_DIM + r1) * H_DIM + c1) * M4 + lane;

    float4 acc = make_float4(-FLT_MAX, -FLT_MAX, -FLT_MAX, -FLT_MAX);

    // 4 rows as 2 row-pairs; per pair 2x10 (+2) independent loads in flight.
    #pragma unroll 1
    for (int rp = 0; rp < 2; ++rp) {
        const float4* r0 = base + (size_t)(2 * rp) * ROW_STRIDE;
        const float4* r1p = r0 + ROW_STRIDE;

        #pragma unroll
        for (int c = 0; c < 10; ++c) {
            float4 va = __ldcs(r0  + (size_t)c * M4);
            float4 vb = __ldcs(r1p + (size_t)c * M4);
            acc = fmax4(acc, fmax4(va, vb));
        }
        if (has11) {
            float4 va = __ldcs(r0  + (size_t)10 * M4);
            float4 vb = __ldcs(r1p + (size_t)10 * M4);
            acc = fmax4(acc, fmax4(va, vb));
        }
    }

    // Merge the two halves through smem (2KB), half 0 stores.
    __shared__ float4 sh[M4];
    if (half == 1) sh[lane] = acc;
    __syncthreads();
    if (half == 0) {
        acc = fmax4(acc, sh[lane]);
        out4[((size_t)b * (W_BINS * H_BINS) + bin) * M4 + lane] = acc;
    }
}

extern "C" void kernel_launch(void* const* d_in, const int* in_sizes, int n_in,
                              void* d_out, int out_size) {
    (void)in_sizes; (void)n_in; (void)out_size;
    const float4* x4 = (const float4*)d_in[0];
    float4* o4 = (float4*)d_out;

    dim3 grid(W_BINS * H_BINS, B_DIM);   // (48, 32) = 1536 blocks
    adaptive_maxpool_kernel<<<grid, 2 * M4>>>(x4, o4);
}